// round 2
// baseline (speedup 1.0000x reference)
#include <cuda_runtime.h>
#include <math.h>

// Problem constants
#define Bn 128
#define Tn 256
#define Hn 1024
#define NCTA 128
#define NTHREADS 256
#define COLS_PER_CTA 8   // 128 CTAs x 8 cols = 1024 output columns
#define KCHUNK 64
#define SA_PITCH 65      // pad to avoid LDS bank conflicts

// Hidden-state double buffers (graph-replay safe: re-initialized each launch)
__device__ __align__(16) float g_h0[2][Bn * Hn];
__device__ __align__(16) float g_h1[2][Bn * Hn];

// Grid barrier state. cnt self-resets to 0 every barrier; gen is monotonic
// (equality-compare only), so state is consistent across graph replays.
__device__ unsigned g_bar_cnt;
__device__ unsigned g_bar_gen;

__device__ __forceinline__ void grid_barrier() {
    __syncthreads();
    if (threadIdx.x == 0) {
        __threadfence();
        unsigned gen = *(volatile unsigned*)&g_bar_gen;
        unsigned arrived = atomicAdd(&g_bar_cnt, 1u);
        if (arrived == NCTA - 1) {
            g_bar_cnt = 0;
            __threadfence();
            atomicAdd(&g_bar_gen, 1u);
        } else {
            while (*(volatile unsigned*)&g_bar_gen == gen) { __nanosleep(32); }
        }
        __threadfence();
    }
    __syncthreads();
}

// Accumulate acc[0..3] += A[r, :] @ W[:, cg..cg+3] for K = Hn,
// staging A tiles (128 x KCHUNK) through shared memory.
__device__ __forceinline__ void accum_mat(float acc[4],
                                          const float* __restrict__ Abase,
                                          size_t strideA,
                                          const float* __restrict__ sW,
                                          float* __restrict__ sA,
                                          int r, int cg, int tid) {
    for (int k0 = 0; k0 < Hn; k0 += KCHUNK) {
        // Cooperative fill: 128 rows x 64 floats = 2048 float4, 8 per thread.
        #pragma unroll
        for (int i = 0; i < (Bn * KCHUNK / 4) / NTHREADS; i++) {
            int idx4 = tid + i * NTHREADS;
            int rr = idx4 >> 4;            // 16 float4 per row
            int kq = (idx4 & 15) << 2;
            const float4 v = *(const float4*)(Abase + (size_t)rr * strideA + k0 + kq);
            float* dst = sA + rr * SA_PITCH + kq;   // pitch 65: scalar stores
            dst[0] = v.x; dst[1] = v.y; dst[2] = v.z; dst[3] = v.w;
        }
        __syncthreads();
        const float* a = sA + r * SA_PITCH;
        const float* w = sW + (size_t)k0 * COLS_PER_CTA + cg;
        #pragma unroll
        for (int kk = 0; kk < KCHUNK; kk++) {
            float av = a[kk];                                   // conflict-free LDS
            float4 wv = *(const float4*)(w + kk * COLS_PER_CTA); // broadcast LDS.128
            acc[0] = fmaf(av, wv.x, acc[0]);
            acc[1] = fmaf(av, wv.y, acc[1]);
            acc[2] = fmaf(av, wv.z, acc[2]);
            acc[3] = fmaf(av, wv.w, acc[3]);
        }
        __syncthreads();
    }
}

extern __shared__ float smem[];

__global__ void __launch_bounds__(NTHREADS, 1)
rnn_persistent_kernel(const float* __restrict__ x,   // [B,T,H]
                      const float* __restrict__ h0,  // [1,L,H]
                      const float* __restrict__ Wi,  // [L,H,H]
                      const float* __restrict__ bi,  // [L,H]
                      const float* __restrict__ Wh,  // [L,H,H]
                      const float* __restrict__ bh,  // [L,H]
                      float* __restrict__ out) {
    // Shared memory layout
    float* sWi0 = smem;                                  // [Hn][8]
    float* sWh0 = sWi0 + Hn * COLS_PER_CTA;
    float* sWi1 = sWh0 + Hn * COLS_PER_CTA;
    float* sWh1 = sWi1 + Hn * COLS_PER_CTA;
    float* sA   = sWh1 + Hn * COLS_PER_CTA;              // [128][65]

    const int tid = threadIdx.x;
    const int cta = blockIdx.x;
    const int c0  = cta * COLS_PER_CTA;                  // global column base
    const int r   = tid & (Bn - 1);                      // batch row (0..127)
    const int cg  = (tid >> 7) * 4;                      // col subgroup: 0 or 4

    // Load this CTA's weight column slices once (resident for whole kernel).
    for (int i = tid; i < Hn * COLS_PER_CTA; i += NTHREADS) {
        int k = i >> 3, c = i & 7;
        size_t gidx = (size_t)k * Hn + c0 + c;
        sWi0[i] = Wi[gidx];
        sWh0[i] = Wh[gidx];
        sWi1[i] = Wi[(size_t)Hn * Hn + gidx];
        sWh1[i] = Wh[(size_t)Hn * Hn + gidx];
    }

    // Initialize hidden-state buffers (phase 0) by broadcasting h0 over batch.
    for (int i = cta * NTHREADS + tid; i < Bn * Hn; i += NCTA * NTHREADS) {
        int h = i & (Hn - 1);
        g_h0[0][i] = h0[h];
        g_h1[0][i] = h0[Hn + h];
    }

    // Per-thread bias registers (input + hidden bias pre-summed).
    float bA[4], bB[4];
    #pragma unroll
    for (int j = 0; j < 4; j++) {
        int c = c0 + cg + j;
        bA[j] = bi[c] + bh[c];
        bB[j] = bi[Hn + c] + bh[Hn + c];
    }

    __syncthreads();     // weights ready within CTA
    grid_barrier();      // hidden-state init visible grid-wide

    float* out_y  = out;                          // [B,T,H]
    float* out_hn = out + (size_t)Bn * Tn * Hn;   // [B,L,H]

    for (int t = 0; t < Tn; t++) {
        const int p = t & 1;

        // ---- Stage A: layer 0  hn0 = tanh(x_t @ Wi0 + h0 @ Wh0 + b) ----
        {
            float acc[4] = {bA[0], bA[1], bA[2], bA[3]};
            accum_mat(acc, x + (size_t)t * Hn, (size_t)Tn * Hn, sWi0, sA, r, cg, tid);
            accum_mat(acc, g_h0[p], Hn, sWh0, sA, r, cg, tid);
            #pragma unroll
            for (int j = 0; j < 4; j++) {
                float v = tanhf(acc[j]);
                g_h0[p ^ 1][(size_t)r * Hn + c0 + cg + j] = v;
                if (t == Tn - 1)
                    out_hn[(size_t)r * 2 * Hn + c0 + cg + j] = v;  // h_n layer 0
            }
        }
        grid_barrier();  // hn0 visible before layer 1 consumes it

        // ---- Stage B: layer 1  hn1 = tanh(hn0 @ Wi1 + h1 @ Wh1 + b) ----
        {
            float acc[4] = {bB[0], bB[1], bB[2], bB[3]};
            accum_mat(acc, g_h0[p ^ 1], Hn, sWi1, sA, r, cg, tid);
            accum_mat(acc, g_h1[p],     Hn, sWh1, sA, r, cg, tid);
            #pragma unroll
            for (int j = 0; j < 4; j++) {
                float v = tanhf(acc[j]);
                g_h1[p ^ 1][(size_t)r * Hn + c0 + cg + j] = v;
                out_y[(size_t)r * Tn * Hn + (size_t)t * Hn + c0 + cg + j] = v;
                if (t == Tn - 1)
                    out_hn[(size_t)r * 2 * Hn + Hn + c0 + cg + j] = v;  // h_n layer 1
            }
        }
        grid_barrier();  // hn1 / h-state visible before next step
    }
}

extern "C" void kernel_launch(void* const* d_in, const int* in_sizes, int n_in,
                              void* d_out, int out_size) {
    const float* x  = (const float*)d_in[0];
    const float* h0 = (const float*)d_in[1];
    const float* Wi = (const float*)d_in[2];
    const float* bi = (const float*)d_in[3];
    const float* Wh = (const float*)d_in[4];
    const float* bh = (const float*)d_in[5];
    float* out = (float*)d_out;

    size_t smem_bytes = (4u * Hn * COLS_PER_CTA + Bn * SA_PITCH) * sizeof(float);
    cudaFuncSetAttribute(rnn_persistent_kernel,
                         cudaFuncAttributeMaxDynamicSharedMemorySize,
                         (int)smem_bytes);
    rnn_persistent_kernel<<<NCTA, NTHREADS, smem_bytes>>>(x, h0, Wi, bi, Wh, bh, out);
}